// round 13
// baseline (speedup 1.0000x reference)
#include <cuda_runtime.h>
#include <cuda_bf16.h>
#include <cuda_fp16.h>
#include <mma.h>
#include <math.h>
#include <cstdint>

using namespace nvcuda;

#define N_NODES 100000
#define IN_F 256
#define HID 128
#define OUT_F 64
#define E_MAX 1600000
#define SCAN_B 1024
#define SCAN_NB ((N_NODES + SCAN_B - 1) / SCAN_B)   // 98

// Scratch (device globals — no allocation allowed in kernel_launch).
__device__ __half g_msgh[(size_t)N_NODES * HID];  // gather array (fp16 messages)
__device__ float  g_acc[(size_t)N_NODES * HID];   // relu(h)+bias after agg1 (fp32)
__device__ int    g_deg_src[N_NODES];
__device__ int    g_deg_dst[N_NODES];
__device__ int    g_off[N_NODES + 1];
__device__ int    g_cursor[N_NODES];
__device__ int    g_csr[E_MAX];
__device__ int    g_bsum[SCAN_NB];
__device__ int    g_boff[SCAN_NB];
// Pre-split transposed weights, [N, K] K-contiguous bf16 (wmma B col_major layout)
__device__ __nv_bfloat16 g_w1hi[HID * IN_F];
__device__ __nv_bfloat16 g_w1lo[HID * IN_F];
__device__ __nv_bfloat16 g_w2hi[HID * HID];
__device__ __nv_bfloat16 g_w2lo[HID * HID];

__device__ __forceinline__ uint32_t pack_bf16x2(float a, float b) {
    __nv_bfloat162 h = __floats2bfloat162_rn(a, b);
    return *reinterpret_cast<uint32_t*>(&h);
}
__device__ __forceinline__ uint32_t pack_half2(float a, float b) {
    __half2 h = __floats2half2_rn(a, b);
    return *reinterpret_cast<uint32_t*>(&h);
}

// ---------------------------------------------------------------------------
// Graph preprocessing
// ---------------------------------------------------------------------------
__global__ void zero_deg_kernel() {
    int i = blockIdx.x * blockDim.x + threadIdx.x;
    if (i < N_NODES) { g_deg_src[i] = 0; g_deg_dst[i] = 0; }
}

__global__ void hist_kernel(const int* __restrict__ src, const int* __restrict__ dst, int E) {
    int i = blockIdx.x * blockDim.x + threadIdx.x;
    if (i < E) {
        atomicAdd(&g_deg_src[src[i]], 1);
        atomicAdd(&g_deg_dst[dst[i]], 1);
    }
}

__global__ void scan1_kernel() {
    __shared__ int sh[SCAN_B];
    int tid = threadIdx.x;
    int i = blockIdx.x * SCAN_B + tid;
    int v = (i < N_NODES) ? g_deg_dst[i] : 0;
    sh[tid] = v;
    __syncthreads();
    for (int off = 1; off < SCAN_B; off <<= 1) {
        int t = (tid >= off) ? sh[tid - off] : 0;
        __syncthreads();
        sh[tid] += t;
        __syncthreads();
    }
    if (i < N_NODES) g_off[i] = sh[tid] - v;
    if (tid == SCAN_B - 1) g_bsum[blockIdx.x] = sh[tid];
}

__global__ void scan2_kernel() {
    __shared__ int sh[128];
    int tid = threadIdx.x;
    int v = (tid < SCAN_NB) ? g_bsum[tid] : 0;
    sh[tid] = v;
    __syncthreads();
    for (int off = 1; off < 128; off <<= 1) {
        int t = (tid >= off) ? sh[tid - off] : 0;
        __syncthreads();
        sh[tid] += t;
        __syncthreads();
    }
    if (tid < SCAN_NB) g_boff[tid] = sh[tid] - v;
}

__global__ void scan3_kernel(int E) {
    int i = blockIdx.x * blockDim.x + threadIdx.x;
    if (i < N_NODES) {
        int off = g_off[i] + g_boff[i / SCAN_B];
        g_off[i] = off;
        g_cursor[i] = off;
    }
    if (i == 0) g_off[N_NODES] = E;
}

__global__ void scatter_kernel(const int* __restrict__ src, const int* __restrict__ dst, int E) {
    int i = blockIdx.x * blockDim.x + threadIdx.x;
    if (i < E) {
        int pos = atomicAdd(&g_cursor[dst[i]], 1);
        g_csr[pos] = src[i];
    }
}

// ---------------------------------------------------------------------------
// Weight preprocessing: transpose to [N, K] and split fp32 -> bf16 hi/lo
// ---------------------------------------------------------------------------
__global__ void pre_w1_kernel(const float* __restrict__ W) {   // W: [256, 128]
    int i = blockIdx.x * blockDim.x + threadIdx.x;
    if (i < IN_F * HID) {
        int k = i / HID, n = i % HID;
        float w = W[i];
        __nv_bfloat16 hi = __float2bfloat16_rn(w);
        float lo = w - __bfloat162float(hi);
        g_w1hi[n * IN_F + k] = hi;
        g_w1lo[n * IN_F + k] = __float2bfloat16_rn(lo);
    }
}

__global__ void pre_w2_kernel(const float* __restrict__ Wmu, const float* __restrict__ Wls) {
    int i = blockIdx.x * blockDim.x + threadIdx.x;
    if (i < HID * HID) {
        int k = i / HID, n = i % HID;
        float w = (n < 64) ? Wmu[k * OUT_F + n] : Wls[k * OUT_F + (n - 64)];
        __nv_bfloat16 hi = __float2bfloat16_rn(w);
        float lo = w - __bfloat162float(hi);
        g_w2hi[n * HID + k] = hi;
        g_w2lo[n * HID + k] = __float2bfloat16_rn(lo);
    }
}

// ---------------------------------------------------------------------------
// wmma split-bf16 GEMM, occupancy-tuned:
//   g_msgh[r,:] = half( (A[r,:] @ W) * (1/max(deg_src[r],1)) )
// CTA 64x128, 8 warps as 2x4 (warp 32 rows x 32 cols, 2x2 frags = 32 acc regs).
// K chunks of 32; serialized staging (R7 structure, measured best).
// D = Ahi*Bhi + Ahi*Blo + Alo*Bhi (fp32 accum).
// ---------------------------------------------------------------------------
#define LDM 40   // bf16 elems per staged row
// smem layout (bytes): sAhi[64*LDM*2]=5120, sAlo=5120, sBhi[128*LDM*2]=10240, sBlo=10240
#define OFF_AHI 0
#define OFF_ALO 5120
#define OFF_BHI 10240
#define OFF_BLO 20480
#define SMEM_BYTES 30720

template <int KT, bool FROM_ACC, bool USE_W2>
__global__ __launch_bounds__(256, 3)
void wmma_gemm_kernel(const float* __restrict__ Aext) {
    __shared__ __align__(16) char smem[SMEM_BYTES];
    __nv_bfloat16* sAhi = (__nv_bfloat16*)(smem + OFF_AHI);
    __nv_bfloat16* sAlo = (__nv_bfloat16*)(smem + OFF_ALO);
    __nv_bfloat16* sBhi = (__nv_bfloat16*)(smem + OFF_BHI);
    __nv_bfloat16* sBlo = (__nv_bfloat16*)(smem + OFF_BLO);

    const float* Asrc = FROM_ACC ? g_acc : Aext;
    const __nv_bfloat16* Whi = USE_W2 ? g_w2hi : g_w1hi;
    const __nv_bfloat16* Wlo = USE_W2 ? g_w2lo : g_w1lo;

    const int tid = threadIdx.x;
    const int wid = tid >> 5;
    const int lane = tid & 31;
    const int wr = wid >> 2;          // 0..1: row group (32 rows)
    const int wc = wid & 3;           // 0..3: col group (32 cols)
    const int row0 = blockIdx.x * 64;

    wmma::fragment<wmma::accumulator, 16, 16, 16, float> acc[2][2];
#pragma unroll
    for (int m = 0; m < 2; m++)
#pragma unroll
        for (int n = 0; n < 2; n++) wmma::fill_fragment(acc[m][n], 0.f);

#pragma unroll 1
    for (int k0 = 0; k0 < KT; k0 += 32) {
        __syncthreads();
        // Stage A: 64 rows x 32 k fp32 -> split bf16 (bit-trick hi/lo). 512 f4.
#pragma unroll
        for (int p = tid; p < 512; p += 256) {
            int r = p >> 3;
            int kk = (p & 7) << 2;
            int grow = row0 + r;
            float4 v = make_float4(0.f, 0.f, 0.f, 0.f);
            if (grow < N_NODES)
                v = *(const float4*)(Asrc + (size_t)grow * KT + k0 + kk);
            uint32_t h0 = pack_bf16x2(v.x, v.y);
            uint32_t h1 = pack_bf16x2(v.z, v.w);
            float hx = __uint_as_float(h0 << 16);
            float hy = __uint_as_float(h0 & 0xffff0000u);
            float hz = __uint_as_float(h1 << 16);
            float hw = __uint_as_float(h1 & 0xffff0000u);
            uint32_t l0 = pack_bf16x2(v.x - hx, v.y - hy);
            uint32_t l1 = pack_bf16x2(v.z - hz, v.w - hw);
            *(uint2*)(sAhi + r * LDM + kk) = make_uint2(h0, h1);
            *(uint2*)(sAlo + r * LDM + kk) = make_uint2(l0, l1);
        }
        // Stage B: 128 n-rows x 32 k bf16 hi/lo.
#pragma unroll
        for (int p = tid; p < 512; p += 256) {
            int n = p >> 2;
            int kk = (p & 3) << 3;
            size_t gsrc = (size_t)n * KT + k0 + kk;
            uint4 vh = *(const uint4*)(Whi + gsrc);
            uint4 vl = *(const uint4*)(Wlo + gsrc);
            *(uint2*)(sBhi + n * LDM + kk)     = make_uint2(vh.x, vh.y);
            *(uint2*)(sBhi + n * LDM + kk + 4) = make_uint2(vh.z, vh.w);
            *(uint2*)(sBlo + n * LDM + kk)     = make_uint2(vl.x, vl.y);
            *(uint2*)(sBlo + n * LDM + kk + 4) = make_uint2(vl.z, vl.w);
        }
        __syncthreads();

#pragma unroll
        for (int ks = 0; ks < 2; ks++) {
            wmma::fragment<wmma::matrix_a, 16, 16, 16, __nv_bfloat16, wmma::row_major> ahi[2], alo[2];
#pragma unroll
            for (int m = 0; m < 2; m++) {
                wmma::load_matrix_sync(ahi[m], sAhi + (wr * 32 + m * 16) * LDM + ks * 16, LDM);
                wmma::load_matrix_sync(alo[m], sAlo + (wr * 32 + m * 16) * LDM + ks * 16, LDM);
            }
#pragma unroll
            for (int nt = 0; nt < 2; nt++) {
                wmma::fragment<wmma::matrix_b, 16, 16, 16, __nv_bfloat16, wmma::col_major> bhi, blo;
                wmma::load_matrix_sync(bhi, sBhi + (wc * 32 + nt * 16) * LDM + ks * 16, LDM);
                wmma::load_matrix_sync(blo, sBlo + (wc * 32 + nt * 16) * LDM + ks * 16, LDM);
#pragma unroll
                for (int m = 0; m < 2; m++) {
                    wmma::mma_sync(acc[m][nt], ahi[m], bhi, acc[m][nt]);
                    wmma::mma_sync(acc[m][nt], ahi[m], blo, acc[m][nt]);
                    wmma::mma_sync(acc[m][nt], alo[m], bhi, acc[m][nt]);
                }
            }
        }
    }

    // Epilogue: bounce frags through smem (8 KB region), scale by norm, fp16 out.
    __syncthreads();
    float* epi = reinterpret_cast<float*>(smem) + wid * 256;
    const int r = lane >> 1;
    const int c = (lane & 1) << 3;
#pragma unroll
    for (int m = 0; m < 2; m++) {
        const int grow = row0 + wr * 32 + m * 16 + r;
        float nv = 0.f;
        if (grow < N_NODES)
            nv = 1.0f / fmaxf((float)g_deg_src[grow], 1.0f);
#pragma unroll
        for (int nt = 0; nt < 2; nt++) {
            wmma::store_matrix_sync(epi, acc[m][nt], 16, wmma::mem_row_major);
            __syncwarp();
            if (grow < N_NODES) {
                float4 v0 = *(float4*)(epi + r * 16 + c);
                float4 v1 = *(float4*)(epi + r * 16 + c + 4);
                uint2 o0 = make_uint2(pack_half2(v0.x * nv, v0.y * nv),
                                      pack_half2(v0.z * nv, v0.w * nv));
                uint2 o1 = make_uint2(pack_half2(v1.x * nv, v1.y * nv),
                                      pack_half2(v1.z * nv, v1.w * nv));
                int jc = wc * 32 + nt * 16 + c;
                *(uint2*)(g_msgh + (size_t)grow * HID + jc)     = o0;
                *(uint2*)(g_msgh + (size_t)grow * HID + jc + 4) = o1;
            }
            __syncwarp();
        }
    }
}

// ---------------------------------------------------------------------------
// CSR aggregation: gather fp16 messages, accumulate fp32.
// One warp per destination node; lane owns cols [4L, 4L+4).
// ---------------------------------------------------------------------------
__device__ __forceinline__ float4 warp_gather_sum(int n, int lane) {
    int beg = g_off[n];
    int end = g_off[n + 1];
    float4 acc = make_float4(0.f, 0.f, 0.f, 0.f);
    for (int base = beg; base < end; base += 32) {
        int idx = base + lane;
        int eid = (idx < end) ? g_csr[idx] : 0;
        int cnt = min(32, end - base);
        for (int k = 0; k < cnt; k++) {
            int s = __shfl_sync(0xffffffffu, eid, k);
            uint2 u = *(const uint2*)(g_msgh + (size_t)s * HID + lane * 4);
            float2 f0 = __half22float2(*reinterpret_cast<__half2*>(&u.x));
            float2 f1 = __half22float2(*reinterpret_cast<__half2*>(&u.y));
            acc.x += f0.x; acc.y += f0.y; acc.z += f1.x; acc.w += f1.y;
        }
    }
    return acc;
}

__global__ void agg1_kernel(const float* __restrict__ bsh) {
    int n = (int)(((size_t)blockIdx.x * blockDim.x + threadIdx.x) >> 5);
    int lane = threadIdx.x & 31;
    if (n >= N_NODES) return;
    float4 acc = warp_gather_sum(n, lane);
    float4 bb = *(const float4*)(bsh + lane * 4);
    float4 o;
    o.x = fmaxf(acc.x + bb.x, 0.f);
    o.y = fmaxf(acc.y + bb.y, 0.f);
    o.z = fmaxf(acc.z + bb.z, 0.f);
    o.w = fmaxf(acc.w + bb.w, 0.f);
    *(float4*)(g_acc + (size_t)n * HID + lane * 4) = o;
}

__global__ void agg2_final_kernel(const float* __restrict__ noise,
                                  const float* __restrict__ bmu,
                                  const float* __restrict__ bls,
                                  float* __restrict__ out) {
    int n = (int)(((size_t)blockIdx.x * blockDim.x + threadIdx.x) >> 5);
    int lane = threadIdx.x & 31;
    if (n >= N_NODES) return;
    float4 acc = warp_gather_sum(n, lane);
    float4 other;
    other.x = __shfl_xor_sync(0xffffffffu, acc.x, 16);
    other.y = __shfl_xor_sync(0xffffffffu, acc.y, 16);
    other.z = __shfl_xor_sync(0xffffffffu, acc.z, 16);
    other.w = __shfl_xor_sync(0xffffffffu, acc.w, 16);
    if (lane < 16) {
        int j = lane * 4;
        float4 bm = *(const float4*)(bmu + j);
        float4 bl = *(const float4*)(bls + j);
        float4 nz = *(const float4*)(noise + (size_t)n * OUT_F + j);
        float4 o;
        o.x = acc.x + bm.x + nz.x * expf(other.x + bl.x);
        o.y = acc.y + bm.y + nz.y * expf(other.y + bl.y);
        o.z = acc.z + bm.z + nz.z * expf(other.z + bl.z);
        o.w = acc.w + bm.w + nz.w * expf(other.w + bl.w);
        *(float4*)(out + (size_t)n * OUT_F + j) = o;
    }
}

// ---------------------------------------------------------------------------
extern "C" void kernel_launch(void* const* d_in, const int* in_sizes, int n_in,
                              void* d_out, int out_size) {
    const float* feat  = (const float*)d_in[0];
    const float* Wsh   = (const float*)d_in[1];
    const float* bsh   = (const float*)d_in[2];
    const float* Wmu   = (const float*)d_in[3];
    const float* bmu   = (const float*)d_in[4];
    const float* Wls   = (const float*)d_in[5];
    const float* bls   = (const float*)d_in[6];
    const float* noise = (const float*)d_in[7];
    const int*   src   = (const int*)d_in[8];
    const int*   dst   = (const int*)d_in[9];
    const int E = in_sizes[8];
    float* out = (float*)d_out;

    const int agg_blocks  = (N_NODES * 32 + 255) / 256;   // warp per node
    const int gemm_blocks = (N_NODES + 63) / 64;          // 1563

    // Launch order: gemm1 is launch #4 (ncu capture slot).
    zero_deg_kernel<<<(N_NODES + 255) / 256, 256>>>();                    // 1
    pre_w1_kernel<<<(IN_F * HID + 255) / 256, 256>>>(Wsh);                // 2
    hist_kernel<<<(E + 255) / 256, 256>>>(src, dst, E);                   // 3
    wmma_gemm_kernel<IN_F, false, false><<<gemm_blocks, 256>>>(feat);     // 4 <- profiled
    pre_w2_kernel<<<(HID * HID + 255) / 256, 256>>>(Wmu, Wls);            // 5
    scan1_kernel<<<SCAN_NB, SCAN_B>>>();                                  // 6
    scan2_kernel<<<1, 128>>>();                                           // 7
    scan3_kernel<<<(N_NODES + 255) / 256, 256>>>(E);                      // 8
    scatter_kernel<<<(E + 255) / 256, 256>>>(src, dst, E);                // 9
    agg1_kernel<<<agg_blocks, 256>>>(bsh);                                // 10
    wmma_gemm_kernel<HID, true, true><<<gemm_blocks, 256>>>(nullptr);     // 11
    agg2_final_kernel<<<agg_blocks, 256>>>(noise, bmu, bls, out);         // 12
}

// round 14
// speedup vs baseline: 1.2911x; 1.2911x over previous
#include <cuda_runtime.h>
#include <cuda_fp16.h>
#include <mma.h>
#include <math.h>
#include <cstdint>

using namespace nvcuda;

#define N_NODES 100000
#define IN_F 256
#define HID 128
#define OUT_F 64
#define E_MAX 1600000
#define SCAN_B 1024
#define SCAN_NB ((N_NODES + SCAN_B - 1) / SCAN_B)   // 98

// Scratch (device globals — no allocation allowed in kernel_launch).
__device__ __half g_msgh[(size_t)N_NODES * HID];  // gather array (fp16 messages)
__device__ float  g_acc[(size_t)N_NODES * HID];   // relu(h)+bias after agg1 (fp32)
__device__ int    g_deg_src[N_NODES];
__device__ int    g_deg_dst[N_NODES];
__device__ int    g_off[N_NODES + 1];
__device__ int    g_cursor[N_NODES];
__device__ int    g_csr[E_MAX];
__device__ int    g_bsum[SCAN_NB];
__device__ int    g_boff[SCAN_NB];
// Pre-transposed fp16 weights, [N, K] K-contiguous (wmma B col_major layout)
__device__ __half g_w1h[HID * IN_F];
__device__ __half g_w2h[HID * HID];

__device__ __forceinline__ uint32_t pack_half2(float a, float b) {
    __half2 h = __floats2half2_rn(a, b);
    return *reinterpret_cast<uint32_t*>(&h);
}

// ---------------------------------------------------------------------------
// Graph preprocessing
// ---------------------------------------------------------------------------
__global__ void zero_deg_kernel() {
    int i = blockIdx.x * blockDim.x + threadIdx.x;
    if (i < N_NODES) { g_deg_src[i] = 0; g_deg_dst[i] = 0; }
}

__global__ void hist_kernel(const int* __restrict__ src, const int* __restrict__ dst, int E) {
    int i = blockIdx.x * blockDim.x + threadIdx.x;
    if (i < E) {
        atomicAdd(&g_deg_src[src[i]], 1);
        atomicAdd(&g_deg_dst[dst[i]], 1);
    }
}

__global__ void scan1_kernel() {
    __shared__ int sh[SCAN_B];
    int tid = threadIdx.x;
    int i = blockIdx.x * SCAN_B + tid;
    int v = (i < N_NODES) ? g_deg_dst[i] : 0;
    sh[tid] = v;
    __syncthreads();
    for (int off = 1; off < SCAN_B; off <<= 1) {
        int t = (tid >= off) ? sh[tid - off] : 0;
        __syncthreads();
        sh[tid] += t;
        __syncthreads();
    }
    if (i < N_NODES) g_off[i] = sh[tid] - v;
    if (tid == SCAN_B - 1) g_bsum[blockIdx.x] = sh[tid];
}

__global__ void scan2_kernel() {
    __shared__ int sh[128];
    int tid = threadIdx.x;
    int v = (tid < SCAN_NB) ? g_bsum[tid] : 0;
    sh[tid] = v;
    __syncthreads();
    for (int off = 1; off < 128; off <<= 1) {
        int t = (tid >= off) ? sh[tid - off] : 0;
        __syncthreads();
        sh[tid] += t;
        __syncthreads();
    }
    if (tid < SCAN_NB) g_boff[tid] = sh[tid] - v;
}

__global__ void scan3_kernel(int E) {
    int i = blockIdx.x * blockDim.x + threadIdx.x;
    if (i < N_NODES) {
        int off = g_off[i] + g_boff[i / SCAN_B];
        g_off[i] = off;
        g_cursor[i] = off;
    }
    if (i == 0) g_off[N_NODES] = E;
}

__global__ void scatter_kernel(const int* __restrict__ src, const int* __restrict__ dst, int E) {
    int i = blockIdx.x * blockDim.x + threadIdx.x;
    if (i < E) {
        int pos = atomicAdd(&g_cursor[dst[i]], 1);
        g_csr[pos] = src[i];
    }
}

// ---------------------------------------------------------------------------
// Weight preprocessing: transpose to [N, K] fp16
// ---------------------------------------------------------------------------
__global__ void pre_w1_kernel(const float* __restrict__ W) {   // W: [256, 128]
    int i = blockIdx.x * blockDim.x + threadIdx.x;
    if (i < IN_F * HID) {
        int k = i / HID, n = i % HID;
        g_w1h[n * IN_F + k] = __float2half_rn(W[i]);
    }
}

__global__ void pre_w2_kernel(const float* __restrict__ Wmu, const float* __restrict__ Wls) {
    int i = blockIdx.x * blockDim.x + threadIdx.x;
    if (i < HID * HID) {
        int k = i / HID, n = i % HID;
        float w = (n < 64) ? Wmu[k * OUT_F + n] : Wls[k * OUT_F + (n - 64)];
        g_w2h[n * HID + k] = __float2half_rn(w);
    }
}

// ---------------------------------------------------------------------------
// Single-MMA fp16 wmma GEMM:
//   g_msgh[r,:] = half( (fp16(A[r,:]) @ fp16(W)) * (1/max(deg_src[r],1)) )
// CTA 128x128, 8 warps as 4x2 (warp 32 rows x 64 cols). K chunks of 32.
// fp32 accumulate.
// ---------------------------------------------------------------------------
#define LDM 40   // fp16 elems per staged row

template <int KT, bool FROM_ACC, bool USE_W2>
__global__ __launch_bounds__(256, 2)
void wmma_gemm_kernel(const float* __restrict__ Aext) {
    __shared__ __align__(16) __half sA[128 * LDM];
    __shared__ __align__(16) __half sB[128 * LDM];

    const float* Asrc = FROM_ACC ? g_acc : Aext;
    const __half* Wh = USE_W2 ? g_w2h : g_w1h;

    const int tid = threadIdx.x;
    const int wid = tid >> 5;
    const int lane = tid & 31;
    const int wr = wid >> 1;          // 0..3: row group (32 rows)
    const int wc = wid & 1;           // 0..1: col group (64 cols)
    const int row0 = blockIdx.x * 128;

    wmma::fragment<wmma::accumulator, 16, 16, 16, float> acc[2][4];
#pragma unroll
    for (int m = 0; m < 2; m++)
#pragma unroll
        for (int n = 0; n < 4; n++) wmma::fill_fragment(acc[m][n], 0.f);

#pragma unroll 1
    for (int k0 = 0; k0 < KT; k0 += 32) {
        __syncthreads();
        // Stage A: 128 rows x 32 k fp32 -> fp16. 1024 float4 loads.
#pragma unroll
        for (int p = tid; p < 1024; p += 256) {
            int r = p >> 3;
            int kk = (p & 7) << 2;
            int grow = row0 + r;
            float4 v = make_float4(0.f, 0.f, 0.f, 0.f);
            if (grow < N_NODES)
                v = *(const float4*)(Asrc + (size_t)grow * KT + k0 + kk);
            *(uint2*)(sA + r * LDM + kk) =
                make_uint2(pack_half2(v.x, v.y), pack_half2(v.z, v.w));
        }
        // Stage B: 128 n-rows x 32 k fp16 (uint4 = 8 halves).
#pragma unroll
        for (int p = tid; p < 512; p += 256) {
            int n = p >> 2;
            int kk = (p & 3) << 3;
            uint4 v = *(const uint4*)(Wh + (size_t)n * KT + k0 + kk);
            *(uint2*)(sB + n * LDM + kk)     = make_uint2(v.x, v.y);
            *(uint2*)(sB + n * LDM + kk + 4) = make_uint2(v.z, v.w);
        }
        __syncthreads();

#pragma unroll
        for (int ks = 0; ks < 2; ks++) {
            wmma::fragment<wmma::matrix_a, 16, 16, 16, __half, wmma::row_major> af[2];
#pragma unroll
            for (int m = 0; m < 2; m++)
                wmma::load_matrix_sync(af[m], sA + (wr * 32 + m * 16) * LDM + ks * 16, LDM);
#pragma unroll
            for (int nt = 0; nt < 4; nt++) {
                wmma::fragment<wmma::matrix_b, 16, 16, 16, __half, wmma::col_major> bf;
                wmma::load_matrix_sync(bf, sB + (wc * 64 + nt * 16) * LDM + ks * 16, LDM);
#pragma unroll
                for (int m = 0; m < 2; m++)
                    wmma::mma_sync(acc[m][nt], af[m], bf, acc[m][nt]);
            }
        }
    }

    // Epilogue: bounce frags through smem (reuse sA), scale by norm, fp16 out.
    __syncthreads();
    float* epi = reinterpret_cast<float*>(sA) + wid * 256;
    const int r = lane >> 1;
    const int c = (lane & 1) << 3;
#pragma unroll
    for (int m = 0; m < 2; m++) {
        const int grow = row0 + wr * 32 + m * 16 + r;
        float nv = 0.f;
        if (grow < N_NODES)
            nv = 1.0f / fmaxf((float)g_deg_src[grow], 1.0f);
#pragma unroll
        for (int nt = 0; nt < 4; nt++) {
            wmma::store_matrix_sync(epi, acc[m][nt], 16, wmma::mem_row_major);
            __syncwarp();
            if (grow < N_NODES) {
                float4 v0 = *(float4*)(epi + r * 16 + c);
                float4 v1 = *(float4*)(epi + r * 16 + c + 4);
                uint4 o;
                o.x = pack_half2(v0.x * nv, v0.y * nv);
                o.y = pack_half2(v0.z * nv, v0.w * nv);
                o.z = pack_half2(v1.x * nv, v1.y * nv);
                o.w = pack_half2(v1.z * nv, v1.w * nv);
                int jc = wc * 64 + nt * 16 + c;
                *(uint4*)(g_msgh + (size_t)grow * HID + jc) = o;
            }
            __syncwarp();
        }
    }
}

// ---------------------------------------------------------------------------
// CSR aggregation: gather fp16 messages, accumulate fp32.
// One warp per destination node; lane owns cols [4L, 4L+4).
// ---------------------------------------------------------------------------
__device__ __forceinline__ float4 warp_gather_sum(int n, int lane) {
    int beg = g_off[n];
    int end = g_off[n + 1];
    float4 acc = make_float4(0.f, 0.f, 0.f, 0.f);
    for (int base = beg; base < end; base += 32) {
        int idx = base + lane;
        int eid = (idx < end) ? g_csr[idx] : 0;
        int cnt = min(32, end - base);
        for (int k = 0; k < cnt; k++) {
            int s = __shfl_sync(0xffffffffu, eid, k);
            uint2 u = *(const uint2*)(g_msgh + (size_t)s * HID + lane * 4);
            float2 f0 = __half22float2(*reinterpret_cast<__half2*>(&u.x));
            float2 f1 = __half22float2(*reinterpret_cast<__half2*>(&u.y));
            acc.x += f0.x; acc.y += f0.y; acc.z += f1.x; acc.w += f1.y;
        }
    }
    return acc;
}

__global__ void agg1_kernel(const float* __restrict__ bsh) {
    int n = (int)(((size_t)blockIdx.x * blockDim.x + threadIdx.x) >> 5);
    int lane = threadIdx.x & 31;
    if (n >= N_NODES) return;
    float4 acc = warp_gather_sum(n, lane);
    float4 bb = *(const float4*)(bsh + lane * 4);
    float4 o;
    o.x = fmaxf(acc.x + bb.x, 0.f);
    o.y = fmaxf(acc.y + bb.y, 0.f);
    o.z = fmaxf(acc.z + bb.z, 0.f);
    o.w = fmaxf(acc.w + bb.w, 0.f);
    *(float4*)(g_acc + (size_t)n * HID + lane * 4) = o;
}

__global__ void agg2_final_kernel(const float* __restrict__ noise,
                                  const float* __restrict__ bmu,
                                  const float* __restrict__ bls,
                                  float* __restrict__ out) {
    int n = (int)(((size_t)blockIdx.x * blockDim.x + threadIdx.x) >> 5);
    int lane = threadIdx.x & 31;
    if (n >= N_NODES) return;
    float4 acc = warp_gather_sum(n, lane);
    float4 other;
    other.x = __shfl_xor_sync(0xffffffffu, acc.x, 16);
    other.y = __shfl_xor_sync(0xffffffffu, acc.y, 16);
    other.z = __shfl_xor_sync(0xffffffffu, acc.z, 16);
    other.w = __shfl_xor_sync(0xffffffffu, acc.w, 16);
    if (lane < 16) {
        int j = lane * 4;
        float4 bm = *(const float4*)(bmu + j);
        float4 bl = *(const float4*)(bls + j);
        float4 nz = *(const float4*)(noise + (size_t)n * OUT_F + j);
        float4 o;
        o.x = acc.x + bm.x + nz.x * expf(other.x + bl.x);
        o.y = acc.y + bm.y + nz.y * expf(other.y + bl.y);
        o.z = acc.z + bm.z + nz.z * expf(other.z + bl.z);
        o.w = acc.w + bm.w + nz.w * expf(other.w + bl.w);
        *(float4*)(out + (size_t)n * OUT_F + j) = o;
    }
}

// ---------------------------------------------------------------------------
extern "C" void kernel_launch(void* const* d_in, const int* in_sizes, int n_in,
                              void* d_out, int out_size) {
    const float* feat  = (const float*)d_in[0];
    const float* Wsh   = (const float*)d_in[1];
    const float* bsh   = (const float*)d_in[2];
    const float* Wmu   = (const float*)d_in[3];
    const float* bmu   = (const float*)d_in[4];
    const float* Wls   = (const float*)d_in[5];
    const float* bls   = (const float*)d_in[6];
    const float* noise = (const float*)d_in[7];
    const int*   src   = (const int*)d_in[8];
    const int*   dst   = (const int*)d_in[9];
    const int E = in_sizes[8];
    float* out = (float*)d_out;

    const int agg_blocks  = (N_NODES * 32 + 255) / 256;   // warp per node
    const int gemm_blocks = (N_NODES + 127) / 128;        // 782

    // Launch order: gemm1 is launch #4 (ncu capture slot).
    zero_deg_kernel<<<(N_NODES + 255) / 256, 256>>>();                    // 1
    pre_w1_kernel<<<(IN_F * HID + 255) / 256, 256>>>(Wsh);                // 2
    hist_kernel<<<(E + 255) / 256, 256>>>(src, dst, E);                   // 3
    wmma_gemm_kernel<IN_F, false, false><<<gemm_blocks, 256>>>(feat);     // 4 <- profiled
    pre_w2_kernel<<<(HID * HID + 255) / 256, 256>>>(Wmu, Wls);            // 5
    scan1_kernel<<<SCAN_NB, SCAN_B>>>();                                  // 6
    scan2_kernel<<<1, 128>>>();                                           // 7
    scan3_kernel<<<(N_NODES + 255) / 256, 256>>>(E);                      // 8
    scatter_kernel<<<(E + 255) / 256, 256>>>(src, dst, E);                // 9
    agg1_kernel<<<agg_blocks, 256>>>(bsh);                                // 10
    wmma_gemm_kernel<HID, true, true><<<gemm_blocks, 256>>>(nullptr);     // 11
    agg2_final_kernel<<<agg_blocks, 256>>>(noise, bmu, bls, out);         // 12
}